// round 5
// baseline (speedup 1.0000x reference)
#include <cuda_runtime.h>
#include <cstdint>
#include <cstddef>

#define BB 2
#define LL 2048
#define HH 16
#define EE 64
#define BS 256
#define NB (LL / BS)                  // 8 blocks
#define OUT_ELEMS (BB * LL * HH * EE) // output tensor precedes attn in d_out

#define QSTRIDE (BS * 16 + 4)         // 4100 floats: 16B skew between quarters
#define SMEM_FLOATS (8 * QSTRIDE)     // K quarters 0..3, V quarters 0..3
typedef unsigned long long ull;

// ---------- packed f32x2 helpers (FFMA2 path, PTX-only) ----------
__device__ __forceinline__ ull pack2(float lo, float hi) {
    ull r;
    asm("mov.b64 %0, {%1, %2};" : "=l"(r) : "f"(lo), "f"(hi));
    return r;
}
__device__ __forceinline__ void unpack2(ull p, float &lo, float &hi) {
    asm("mov.b64 {%0, %1}, %2;" : "=f"(lo), "=f"(hi) : "l"(p));
}
__device__ __forceinline__ void fma2(ull &d, ull a, ull b) {
    asm("fma.rn.f32x2 %0, %1, %2, %0;" : "+l"(d) : "l"(a), "l"(b));
}
__device__ __forceinline__ void add2(ull &d, ull a) {
    asm("add.rn.f32x2 %0, %0, %1;" : "+l"(d) : "l"(a));
}

// ================= kernel 1: streaming zero-fill of off-diagonal attn =================
// grid = 32 (b*h) x 32 slabs of 64 rows; 512 threads; 56 float4 per thread.
// All stores are full 128B-line runs (diag gap is 1KB-aligned).
__global__ void __launch_bounds__(512)
zero_offdiag_kernel(float *__restrict__ out) {
    const int bh   = blockIdx.x >> 5;
    const int slab = blockIdx.x & 31;
    float *base = out + OUT_ELEMS + (size_t)bh * LL * LL;
    const int row_base = slab * 64;
    const int tid = threadIdx.x;
    #pragma unroll
    for (int i = 0; i < 56; i++) {
        int idx  = i * 512 + tid;          // 0..28671 = 64 rows x 448 f4
        int lrow = idx / 448;
        int c4   = idx - lrow * 448;
        int row  = row_base + lrow;
        int blk64 = (row >> 8) << 6;       // diag block start, f4 units
        c4 = (c4 >= blk64) ? c4 + 64 : c4;
        __stcs((float4 *)(base + (size_t)row * LL + c4 * 4),
               make_float4(0.f, 0.f, 0.f, 0.f));
    }
}

// ================= kernel 2: block-diagonal attention =================
extern __shared__ float smem[];

__global__ void __launch_bounds__(512, 1)
sparse_attn_kernel(const float *__restrict__ Q,
                   const float *__restrict__ K,
                   const float *__restrict__ V,
                   float *__restrict__ out) {
    const int tid = threadIdx.x;
    const int bid = blockIdx.x;
    const int blk = bid & (NB - 1);
    const int h   = (bid / NB) & (HH - 1);
    const int b   = bid / (NB * HH);

    const int p    = tid & 3;   // E-quarter this thread owns
    const int rp   = tid >> 2;  // row-pair index (0..127)
    const int row0 = rp * 2;    // local query rows row0, row0+1
    const int rsel = p >> 1;    // row this lane's reduction produces (0 or 1)
    const int hsel = p & 1;     // which half of the 8-key chunk this lane stores
    const bool low = (rsel == 0);

    // ---- stage K,V block into quarter-split, skewed smem ----
    {
        #pragma unroll
        for (int i = 0; i < 8; i++) {
            int idx = i * 512 + tid;       // 4096 float4 per tensor
            int row = idx >> 4;
            int c4  = idx & 15;
            int qt  = c4 >> 2;
            int cc  = (c4 & 3) * 4;
            size_t g = (((size_t)b * LL + blk * BS + row) * HH + h) * EE + c4 * 4;
            *(float4 *)(smem + qt * QSTRIDE + row * 16 + cc) =
                *(const float4 *)(K + g);
            *(float4 *)(smem + 4 * QSTRIDE + qt * QSTRIDE + row * 16 + cc) =
                *(const float4 *)(V + g);
        }
    }
    __syncthreads();

    const float *sKq = smem + p * QSTRIDE;
    const float *sVq = smem + 4 * QSTRIDE + p * QSTRIDE;

    // ---- load both query rows' quarter into packed registers ----
    ull q0[8], q1[8];
    {
        const ulonglong2 *qp0 =
            (const ulonglong2 *)(Q + (((size_t)b * LL + blk * BS + row0) * HH + h) * EE + p * 16);
        const ulonglong2 *qp1 =
            (const ulonglong2 *)(Q + (((size_t)b * LL + blk * BS + row0 + 1) * HH + h) * EE + p * 16);
        #pragma unroll
        for (int i = 0; i < 4; i++) {
            ulonglong2 t0 = qp0[i];
            ulonglong2 t1 = qp1[i];
            q0[2 * i] = t0.x; q0[2 * i + 1] = t0.y;
            q1[2 * i] = t1.x; q1[2 * i + 1] = t1.y;
        }
    }

    ull o0[8], o1[8];
    #pragma unroll
    for (int i = 0; i < 8; i++) { o0[i] = 0ULL; o1[i] = 0ULL; }
    float lsum_m = 0.f;  // sum of e for MY row (row0+rsel)
    float lsum_o = 0.f;  // sum of e for the other row

    const size_t abase = (size_t)OUT_ELEMS + (size_t)(b * HH + h) * LL * LL;
    float *attn_mine = out + abase + (size_t)(blk * BS + row0 + rsel) * LL + (size_t)blk * BS;

    // ---- main loop: 32 chunks x 8 keys, phase-batched ----
    for (int ch = 0; ch < 32; ch++) {
        // phase 1: partial dots for 8 keys, both rows
        float t8[8], u8[8]; // t = partial of MY row, u = partial of other row
        #pragma unroll
        for (int jj = 0; jj < 8; jj++) {
            const int j = ch * 8 + jj;
            const ulonglong2 *kp = (const ulonglong2 *)(sKq + j * 16);
            ull a0 = 0, a1 = 0, b0 = 0, b1 = 0;
            #pragma unroll
            for (int i = 0; i < 4; i++) {
                ulonglong2 kk = kp[i];
                fma2(a0, q0[2 * i],     kk.x);
                fma2(a1, q0[2 * i + 1], kk.y);
                fma2(b0, q1[2 * i],     kk.x);
                fma2(b1, q1[2 * i + 1], kk.y);
            }
            add2(a0, a1);
            add2(b0, b1);
            float l0, h0, l1, h1;
            unpack2(a0, l0, h0);
            unpack2(b0, l1, h1);
            float s0 = l0 + h0;
            float s1 = l1 + h1;
            t8[jj] = low ? s0 : s1;
            u8[jj] = low ? s1 : s0;
        }
        // phase 2: 8 independent transpose-reductions (latency overlapped)
        float em[8];
        #pragma unroll
        for (int jj = 0; jj < 8; jj++) {
            float v = t8[jj] + __shfl_xor_sync(0xffffffffu, u8[jj], 2);
            v += __shfl_xor_sync(0xffffffffu, v, 1);
            em[jj] = __expf(v);     // e of MY row; bit-identical within lane pair
        }
        // phase 3: broadcast partner's e, accumulate V for both rows
        #pragma unroll
        for (int jj = 0; jj < 8; jj++) {
            float eo = __shfl_xor_sync(0xffffffffu, em[jj], 2);
            lsum_m += em[jj];
            lsum_o += eo;
            float e0 = low ? em[jj] : eo;
            float e1 = low ? eo : em[jj];
            ull e0v = pack2(e0, e0);
            ull e1v = pack2(e1, e1);
            const ulonglong2 *vp = (const ulonglong2 *)(sVq + (ch * 8 + jj) * 16);
            #pragma unroll
            for (int i = 0; i < 4; i++) {
                ulonglong2 vv = vp[i];
                fma2(o0[2 * i],     vv.x, e0v);
                fma2(o0[2 * i + 1], vv.y, e0v);
                fma2(o1[2 * i],     vv.x, e1v);
                fma2(o1[2 * i + 1], vv.y, e1v);
            }
        }
        // diag e-store: lane stores keys [ch*8 + hsel*4 .. +3] of its row (unnormalized)
        *(float4 *)(attn_mine + ch * 8 + hsel * 4) =
            make_float4(em[hsel * 4], em[hsel * 4 + 1],
                        em[hsel * 4 + 2], em[hsel * 4 + 3]);
    }

    const float recip_m = 1.0f / lsum_m;
    const float recip_o = 1.0f / lsum_o;
    const float recip0 = low ? recip_m : recip_o;
    const float recip1 = low ? recip_o : recip_m;

    // ---- write output: 2 rows x this thread's E-quarter ----
    {
        float *op0 = out + (((size_t)b * LL + blk * BS + row0) * HH + h) * EE + p * 16;
        float *op1 = out + (((size_t)b * LL + blk * BS + row0 + 1) * HH + h) * EE + p * 16;
        #pragma unroll
        for (int i = 0; i < 4; i++) {
            float x0, x1, x2, x3;
            unpack2(o0[2 * i],     x0, x1);
            unpack2(o0[2 * i + 1], x2, x3);
            __stcs((float4 *)(op0 + i * 4),
                   make_float4(x0 * recip0, x1 * recip0, x2 * recip0, x3 * recip0));
            unpack2(o1[2 * i],     x0, x1);
            unpack2(o1[2 * i + 1], x2, x3);
            __stcs((float4 *)(op1 + i * 4),
                   make_float4(x0 * recip1, x1 * recip1, x2 * recip1, x3 * recip1));
        }
    }

    // ---- normalize this lane's (row, half) of the attn diag block in place ----
    {
        float4 *ap = (float4 *)(attn_mine + hsel * 128);
        #pragma unroll 8
        for (int i = 0; i < 32; i++) {
            float4 v = ap[i];
            v.x *= recip_m; v.y *= recip_m; v.z *= recip_m; v.w *= recip_m;
            ap[i] = v;
        }
    }
}

extern "C" void kernel_launch(void *const *d_in, const int *in_sizes, int n_in,
                              void *d_out, int out_size) {
    const float *Q = (const float *)d_in[0];
    const float *K = (const float *)d_in[1];
    const float *V = (const float *)d_in[2];
    float *out = (float *)d_out;

    zero_offdiag_kernel<<<1024, 512>>>(out);

    const int smem_bytes = SMEM_FLOATS * (int)sizeof(float); // 131200
    cudaFuncSetAttribute(sparse_attn_kernel,
                         cudaFuncAttributeMaxDynamicSharedMemorySize, smem_bytes);
    sparse_attn_kernel<<<BB * HH * NB, 512, smem_bytes>>>(Q, K, V, out);
}